// round 10
// baseline (speedup 1.0000x reference)
#include <cuda_runtime.h>

#define TT 512
#define BB 64
#define II 512
#define HH 512

// smem layout (element strides)
#define WSS 34      // float2 stride per k2 row of weights (32 used)
#define HSS 259     // float2 stride per batch row of h (odd => bank rotation)
#define PS  260     // ull stride per ks-plane in reduction array (256 used)
#define WS_BYTES (256 * WSS * 8)             // 69632
#define HSH_BYTES (8 * HSS * 8)              // 16576 per half
#define HSA_OFF  WS_BYTES
#define HSB_OFF  (HSA_OFF + HSH_BYTES)
#define RED_OFF  (HSB_OFF + HSH_BYTES)       // 102784 (16B aligned)
#define SMEM_TOTAL (RED_OFF + 8 * PS * 8)    // 119424

// Static device scratch (no allocations allowed)
__device__ float g_xp[2][TT][BB][HH];      // input projections per direction
__device__ float g_h[2][2][BB][HH];        // [dir][buf][b][h] double-buffered state
__device__ unsigned g_flag[2][2][64][32];  // [dir][half][slice] flags, 128B padded

typedef unsigned long long ull;

__device__ __forceinline__ void fma2(ull& acc, ull a, ull b) {
    asm("fma.rn.f32x2 %0, %1, %2, %0;" : "+l"(acc) : "l"(a), "l"(b));
}
__device__ __forceinline__ ull add2(ull a, ull b) {
    ull r; asm("add.rn.f32x2 %0, %1, %2;" : "=l"(r) : "l"(a), "l"(b)); return r;
}
__device__ __forceinline__ float2 unpack2(ull v) {
    float2 r; asm("mov.b64 {%0, %1}, %2;" : "=f"(r.x), "=f"(r.y) : "l"(v)); return r;
}
__device__ __forceinline__ unsigned ld_acq(const unsigned* p) {
    unsigned v; asm volatile("ld.acquire.gpu.u32 %0, [%1];" : "=r"(v) : "l"(p) : "memory");
    return v;
}
__device__ __forceinline__ void st_rel(unsigned* p, unsigned v) {
    asm volatile("st.release.gpu.u32 [%0], %1;" :: "l"(p), "r"(v) : "memory");
}

// ---------------------------------------------------------------------------
// Phase 1: xp[dir][t][b][n] = sum_i x[b][t][i] * W[n][i] + bias[n]
// ---------------------------------------------------------------------------
__global__ __launch_bounds__(256) void xproj_kernel(
    const float* __restrict__ x,
    const float* __restrict__ Wf, const float* __restrict__ bf,
    const float* __restrict__ Wb, const float* __restrict__ bbias) {
    const int dir = blockIdx.z;
    const float* __restrict__ W    = dir ? Wb : Wf;
    const float* __restrict__ bias = dir ? bbias : bf;
    const int t = blockIdx.y;
    const int n_base = blockIdx.x * 64;

    __shared__ float2 a2[8][66];   // [k2][m]
    __shared__ float2 b2[8][66];   // [k2][n]

    const int tid = threadIdx.x;
    const int w = tid >> 5, lane = tid & 31;
    const int mgrp = ((w >> 1) << 2) | (lane >> 3);  // 0..15
    const int ngrp = ((w & 1) << 3) | (lane & 7);    // 0..15
    const int m0 = mgrp << 2, n0l = ngrp << 2;

    const int lr = tid >> 2;
    const int lq = (tid & 3) << 2;
    const float* arow = x + ((size_t)lr * TT + t) * II + lq;
    const float* brow = W + (size_t)(n_base + lr) * II + lq;

    ull acc[4][4];
#pragma unroll
    for (int i = 0; i < 4; i++)
#pragma unroll
        for (int j = 0; j < 4; j++) acc[i][j] = 0ull;

    for (int st = 0; st < 32; st++) {
        float4 pa = *(const float4*)(arow + st * 16);
        float4 pb = *(const float4*)(brow + st * 16);
        __syncthreads();
        a2[(lq >> 1) + 0][lr] = make_float2(pa.x, pa.y);
        a2[(lq >> 1) + 1][lr] = make_float2(pa.z, pa.w);
        b2[(lq >> 1) + 0][lr] = make_float2(pb.x, pb.y);
        b2[(lq >> 1) + 1][lr] = make_float2(pb.z, pb.w);
        __syncthreads();
#pragma unroll
        for (int k2 = 0; k2 < 8; k2++) {
            ulonglong2 av0 = *(const ulonglong2*)&a2[k2][m0];
            ulonglong2 av1 = *(const ulonglong2*)&a2[k2][m0 + 2];
            ulonglong2 bv0 = *(const ulonglong2*)&b2[k2][n0l];
            ulonglong2 bv1 = *(const ulonglong2*)&b2[k2][n0l + 2];
            ull am[4] = {av0.x, av0.y, av1.x, av1.y};
            ull bn[4] = {bv0.x, bv0.y, bv1.x, bv1.y};
#pragma unroll
            for (int i = 0; i < 4; i++)
#pragma unroll
                for (int j = 0; j < 4; j++)
                    fma2(acc[i][j], am[i], bn[j]);
        }
    }

    float4 bv = *(const float4*)(bias + n_base + n0l);
#pragma unroll
    for (int i = 0; i < 4; i++) {
        float2 s0 = unpack2(acc[i][0]);
        float2 s1 = unpack2(acc[i][1]);
        float2 s2 = unpack2(acc[i][2]);
        float2 s3 = unpack2(acc[i][3]);
        float4 v;
        v.x = s0.x + s0.y + bv.x;
        v.y = s1.x + s1.y + bv.y;
        v.z = s2.x + s2.y + bv.z;
        v.w = s3.x + s3.y + bv.w;
        *(float4*)&g_xp[dir][t][m0 + i][n_base + n0l] = v;
    }
}

// ---------------------------------------------------------------------------
// Phase 2: persistent recurrence, half-batch pipelined.
// 128 CTAs (64/dir), 256 threads, 1 CTA/SM. CTA tile 16b x 32n split into two
// 8b halves; per-half flags give each release a half-block of slack.
// Thread tile per half: 2b x 4n; k-split 8 (one k-slice per warp).
// ---------------------------------------------------------------------------
__global__ __launch_bounds__(256, 1) void rnn_persist(
    const float* __restrict__ Whf, const float* __restrict__ Whb,
    const float* __restrict__ h0f, const float* __restrict__ h0b,
    float* __restrict__ out) {
    extern __shared__ char smem[];
    float2* ws = (float2*)smem;                    // [256][WSS]
    ull* red   = (ull*)(smem + RED_OFF);           // [8 ks][PS]

    const int cta = blockIdx.x;
    const int dir = cta & 1;
    const int slice = cta >> 1;             // 0..63
    const int grp = slice >> 4;             // b-group 0..3
    const int b_base = grp * 16;
    const int n_base = (slice & 15) * 32;
    const float* __restrict__ Wh = dir ? Whb : Whf;
    const float* __restrict__ h0 = dir ? h0b : h0f;
    const int tid = threadIdx.x;
    const int ks = tid >> 5;                // warp id = k-slice (k2 in [32ks,32ks+32))
    const int lane = tid & 31;
    const int ngrp = lane >> 2;             // 0..7  (4 n each)
    const int bgrp = lane & 3;              // 0..3  (2 b each per half)

    // one-time weight fill: ws[k2][nl] = {W[n][2k2], W[n][2k2+1]}
    for (int idx = tid; idx < 32 * 256; idx += 256) {
        int nl = idx >> 8, k2 = idx & 255;
        ws[k2 * WSS + nl] =
            *(const float2*)(Wh + (size_t)(n_base + nl) * HH + 2 * k2);
    }

    // reducer: one output per thread
    const int rbl = tid >> 5;               // local b row 0..7
    const int rnl = tid & 31;               // local n 0..31
    const int rn = n_base + rnl;

    // staging: row sbr (0..7), 4 float4 chunks at c = sc + 32*i
    const int sbr = tid >> 5;
    const int sc = tid & 31;
    const int prod0 = sc >> 3;              // producer slice (local) of chunk i=0

    const float2* wp = ws + (size_t)(ks * 32) * WSS + 4 * ngrp;

    // replay-monotonic barrier base (only this CTA writes its flags)
    const unsigned base = ld_acq(&g_flag[dir][0][slice][0]);
    __syncthreads();

    const int outpos0 = (2 * bgrp) * 32 + 4 * ngrp;   // for red writes

    for (int s = 0; s < TT; s++) {
        const int t = dir ? (TT - 1 - s) : s;
        const float* __restrict__ hin = (const float*)g_h[dir][s & 1];
        float* __restrict__ hout = (float*)g_h[dir][(s & 1) ^ 1];

#pragma unroll 1
        for (int hf = 0; hf < 2; hf++) {
            float2* hs = (float2*)(smem + (hf ? HSB_OFF : HSA_OFF));
            const int hb_base = b_base + 8 * hf;

            // ---- stage 8 x 512 h with producer-precise acquire ----
            if (s == 0) {
#pragma unroll
                for (int i = 0; i < 4; i++) {
                    int c = sc + 32 * i;
                    float4 v = *(const float4*)(h0 + (size_t)(hb_base + sbr) * HH + 4 * c);
                    hs[sbr * HSS + 2 * c]     = make_float2(v.x, v.y);
                    hs[sbr * HSS + 2 * c + 1] = make_float2(v.z, v.w);
                }
            } else {
                const unsigned tgt = base + (unsigned)s;
#pragma unroll
                for (int i = 0; i < 4; i++) {
                    const unsigned* f = &g_flag[dir][hf][grp * 16 + prod0 + 4 * i][0];
                    while (ld_acq(f) < tgt) {}
                    int c = sc + 32 * i;
                    float4 v = *(const float4*)(hin + (size_t)(hb_base + sbr) * HH + 4 * c);
                    hs[sbr * HSS + 2 * c]     = make_float2(v.x, v.y);
                    hs[sbr * HSS + 2 * c + 1] = make_float2(v.z, v.w);
                }
            }
            float xpv = g_xp[dir][t][hb_base + rbl][rn];
            __syncthreads();

            // ---- mainloop: 2b x 4n per thread over this warp's 32 k2 ----
            const float2* hp = hs + (size_t)(2 * bgrp) * HSS + ks * 32;
            ull acc[8];
#pragma unroll
            for (int i = 0; i < 8; i++) acc[i] = 0ull;
#pragma unroll 8
            for (int kk = 0; kk < 32; kk++) {
                ull hv0 = *(const ull*)(hp + kk);
                ull hv1 = *(const ull*)(hp + kk + HSS);
                ulonglong2 w01 = *(const ulonglong2*)(wp + (size_t)kk * WSS);
                ulonglong2 w23 = *(const ulonglong2*)(wp + (size_t)kk * WSS + 2);
                fma2(acc[0], hv0, w01.x); fma2(acc[1], hv0, w01.y);
                fma2(acc[2], hv0, w23.x); fma2(acc[3], hv0, w23.y);
                fma2(acc[4], hv1, w01.x); fma2(acc[5], hv1, w01.y);
                fma2(acc[6], hv1, w23.x); fma2(acc[7], hv1, w23.y);
            }

            // ---- partials: red[ks][outpos], 4 STS.128 ----
            {
                ull* rp = red + (size_t)ks * PS + outpos0;
                *(ulonglong2*)(rp)          = make_ulonglong2(acc[0], acc[1]);
                *(ulonglong2*)(rp + 2)      = make_ulonglong2(acc[2], acc[3]);
                *(ulonglong2*)(rp + 32)     = make_ulonglong2(acc[4], acc[5]);
                *(ulonglong2*)(rp + 34)     = make_ulonglong2(acc[6], acc[7]);
            }
            __syncthreads();

            // ---- 8-way reduce (1 output/thread) + tanh + stores ----
            ull ssum = red[tid];
#pragma unroll
            for (int k = 1; k < 8; k++) ssum = add2(ssum, red[k * PS + tid]);
            float2 f2 = unpack2(ssum);
            float v = tanhf(f2.x + f2.y + xpv);
            const int rb = hb_base + rbl;
            if (s < TT - 1) hout[(size_t)rb * HH + rn] = v;
            __syncthreads();   // hout issued by all; also protects red reuse
            if (s < TT - 1) {
                if (tid == 0) st_rel(&g_flag[dir][hf][slice][0], base + s + 1);
                out[((size_t)rb * TT + t) * (2 * HH) + (size_t)dir * HH + rn] = v;
            } else {
                out[((size_t)rb * TT + t) * (2 * HH) + (size_t)dir * HH + rn] = v;
                float* hT = out + (size_t)BB * TT * 2 * HH + (size_t)dir * BB * HH;
                hT[(size_t)rb * HH + rn] = v;
            }
        }
    }
}

extern "C" void kernel_launch(void* const* d_in, const int* in_sizes, int n_in,
                              void* d_out, int out_size) {
    const float* x     = (const float*)d_in[0];
    const float* h0f   = (const float*)d_in[1];
    const float* h0b   = (const float*)d_in[2];
    const float* Wxf_w = (const float*)d_in[3];
    const float* Wxf_b = (const float*)d_in[4];
    const float* Whf_w = (const float*)d_in[5];
    const float* Wxb_w = (const float*)d_in[6];
    const float* Wxb_b = (const float*)d_in[7];
    const float* Whb_w = (const float*)d_in[8];
    float* out = (float*)d_out;

    static int smem_set = 0;
    if (!smem_set) {
        cudaFuncSetAttribute(rnn_persist,
                             cudaFuncAttributeMaxDynamicSharedMemorySize,
                             SMEM_TOTAL);
        smem_set = 1;
    }

    xproj_kernel<<<dim3(HH / 64, TT, 2), 256>>>(x, Wxf_w, Wxf_b, Wxb_w, Wxb_b);
    rnn_persist<<<128, 256, SMEM_TOTAL>>>(Whf_w, Whb_w, h0f, h0b, out);
}

// round 11
// speedup vs baseline: 1.0583x; 1.0583x over previous
#include <cuda_runtime.h>

#define TT 512
#define BB 64
#define II 512
#define HH 512

// rnn_persist smem layout
#define WSS 74      // float2 stride per k2 row of weights (72 used, group-swizzled)
#define HS2 258     // float2 stride per batch row of h (even => 16B-aligned rows)
#define RROW 70     // ull stride per b_local row in reduction plane
#define RPLANE 560  // ull stride per ks plane (8 * RROW)
#define WS_BYTES (256 * WSS * 8)           // 151552
#define HSB_BYTES (8 * HS2 * 8)            // 16512
#define HSA_OFF  WS_BYTES
#define HSB_OFF  (HSA_OFF + HSB_BYTES)     // 168064
#define RED_OFF  (HSB_OFF + HSB_BYTES)     // 184576
#define SMEM_TOTAL (RED_OFF + 4 * RPLANE * 8)  // 202496

// Static device scratch (no allocations allowed)
__device__ float g_xp[2][TT][BB][HH];    // input projections per direction

typedef unsigned long long ull;

__device__ __forceinline__ void fma2(ull& acc, ull a, ull b) {
    asm("fma.rn.f32x2 %0, %1, %2, %0;" : "+l"(acc) : "l"(a), "l"(b));
}
__device__ __forceinline__ ull add2(ull a, ull b) {
    ull r; asm("add.rn.f32x2 %0, %1, %2;" : "=l"(r) : "l"(a), "l"(b)); return r;
}
__device__ __forceinline__ float2 unpack2(ull v) {
    float2 r; asm("mov.b64 {%0, %1}, %2;" : "=f"(r.x), "=f"(r.y) : "l"(v)); return r;
}
__device__ __forceinline__ unsigned smem_u32(const void* p) {
    unsigned a;
    asm("{ .reg .u64 t; cvta.to.shared.u64 t, %1; cvt.u32.u64 %0, t; }"
        : "=r"(a) : "l"(p));
    return a;
}

// ---------------------------------------------------------------------------
// Phase 1: xp[dir][t][b][n] = sum_i x[b][t][i] * W[n][i] + bias[n]
// ---------------------------------------------------------------------------
__global__ __launch_bounds__(256) void xproj_kernel(
    const float* __restrict__ x,
    const float* __restrict__ Wf, const float* __restrict__ bf,
    const float* __restrict__ Wb, const float* __restrict__ bbias) {
    const int dir = blockIdx.z;
    const float* __restrict__ W    = dir ? Wb : Wf;
    const float* __restrict__ bias = dir ? bbias : bf;
    const int t = blockIdx.y;
    const int n_base = blockIdx.x * 64;

    __shared__ float2 a2[8][66];   // [k2][m]
    __shared__ float2 b2[8][66];   // [k2][n]

    const int tid = threadIdx.x;
    const int w = tid >> 5, lane = tid & 31;
    const int mgrp = ((w >> 1) << 2) | (lane >> 3);  // 0..15
    const int ngrp = ((w & 1) << 3) | (lane & 7);    // 0..15
    const int m0 = mgrp << 2, n0l = ngrp << 2;

    const int lr = tid >> 2;
    const int lq = (tid & 3) << 2;
    const float* arow = x + ((size_t)lr * TT + t) * II + lq;
    const float* brow = W + (size_t)(n_base + lr) * II + lq;

    ull acc[4][4];
#pragma unroll
    for (int i = 0; i < 4; i++)
#pragma unroll
        for (int j = 0; j < 4; j++) acc[i][j] = 0ull;

    for (int st = 0; st < 32; st++) {
        float4 pa = *(const float4*)(arow + st * 16);
        float4 pb = *(const float4*)(brow + st * 16);
        __syncthreads();
        a2[(lq >> 1) + 0][lr] = make_float2(pa.x, pa.y);
        a2[(lq >> 1) + 1][lr] = make_float2(pa.z, pa.w);
        b2[(lq >> 1) + 0][lr] = make_float2(pb.x, pb.y);
        b2[(lq >> 1) + 1][lr] = make_float2(pb.z, pb.w);
        __syncthreads();
#pragma unroll
        for (int k2 = 0; k2 < 8; k2++) {
            ulonglong2 av0 = *(const ulonglong2*)&a2[k2][m0];
            ulonglong2 av1 = *(const ulonglong2*)&a2[k2][m0 + 2];
            ulonglong2 bv0 = *(const ulonglong2*)&b2[k2][n0l];
            ulonglong2 bv1 = *(const ulonglong2*)&b2[k2][n0l + 2];
            ull am[4] = {av0.x, av0.y, av1.x, av1.y};
            ull bn[4] = {bv0.x, bv0.y, bv1.x, bv1.y};
#pragma unroll
            for (int i = 0; i < 4; i++)
#pragma unroll
                for (int j = 0; j < 4; j++)
                    fma2(acc[i][j], am[i], bn[j]);
        }
    }

    float4 bv = *(const float4*)(bias + n_base + n0l);
#pragma unroll
    for (int i = 0; i < 4; i++) {
        float2 s0 = unpack2(acc[i][0]);
        float2 s1 = unpack2(acc[i][1]);
        float2 s2 = unpack2(acc[i][2]);
        float2 s3 = unpack2(acc[i][3]);
        float4 v;
        v.x = s0.x + s0.y + bv.x;
        v.y = s1.x + s1.y + bv.y;
        v.z = s2.x + s2.y + bv.z;
        v.w = s3.x + s3.y + bv.w;
        *(float4*)&g_xp[dir][t][m0 + i][n_base + n0l] = v;
    }
}

// ---------------------------------------------------------------------------
// Phase 2: persistent recurrence with DSMEM clusters.
// 128 CTAs = 16 independent clusters of 8 (one per (dir, b-group)).
// CTA tile 8b x 64n; rank ns owns n cols [64ns, 64ns+64).
// Per step: mainloop (k-split 4, thread 2b x 4n) -> reduce -> tanh ->
// push own 8x64 h slice into all 8 cluster CTAs' next h buffer -> cluster bar.
// No global h traffic, no flags, no polls.
// ---------------------------------------------------------------------------
__global__ __launch_bounds__(256, 1) __cluster_dims__(8, 1, 1)
void rnn_persist(
    const float* __restrict__ Whf, const float* __restrict__ Whb,
    const float* __restrict__ h0f, const float* __restrict__ h0b,
    float* __restrict__ out) {
    extern __shared__ char smem[];
    float2* ws = (float2*)smem;                       // [256][WSS] swizzled
    float2* hsA = (float2*)(smem + HSA_OFF);          // [8][HS2]
    float2* hsB = (float2*)(smem + HSB_OFF);          // [8][HS2]
    ull* red    = (ull*)(smem + RED_OFF);             // [4][RPLANE]

    const int bx = blockIdx.x;
    const int dir = bx >> 6;                // 0..1
    const int bg  = (bx >> 3) & 7;          // b-group 0..7
    const int ns  = bx & 7;                 // cluster rank / n-slice 0..7
    const int b_base = 8 * bg;
    const int n_base = 64 * ns;
    const float* __restrict__ Wh = dir ? Whb : Whf;
    const float* __restrict__ h0 = dir ? h0b : h0f;
    const int tid = threadIdx.x;
    const int wid = tid >> 5, lane = tid & 31;
    const int ks = wid >> 1;                // k-slice 0..3 (k2 in [64ks, 64ks+64))
    const int nh = wid & 1;                 // n-half 0..1 (32 n each)
    const int ngrp = lane >> 2;             // 0..7 (4 n each)
    const int bgrp = lane & 3;              // 0..3 (2 b each)

    const unsigned smem_base = smem_u32(smem);

    // one-time weight fill, group-swizzled so mainloop w LDS.128 is 1 wavefront:
    // nl -> f2 idx = (nl>>5)*36 + 4*((nl>>2)&7) + 2*(((nl>>2)&7)>>2) + (nl&3)
    for (int idx = tid; idx < 64 * 256; idx += 256) {
        int nl = idx >> 8, k2 = idx & 255;
        int g = (nl >> 2) & 7;
        int f2 = (nl >> 5) * 36 + 4 * g + 2 * (g >> 2) + (nl & 3);
        ws[k2 * WSS + f2] =
            *(const float2*)(Wh + (size_t)(n_base + nl) * HH + 2 * k2);
    }

    // stage h0 into hsA: rows 0..7, 128 float4 chunks per row
    {
        int sbr = tid >> 5, sc = tid & 31;
#pragma unroll
        for (int i = 0; i < 4; i++) {
            int c = sc + 32 * i;
            float4 v = *(const float4*)(h0 + (size_t)(b_base + sbr) * HH + 4 * c);
            *(float4*)&hsA[sbr * HS2 + 2 * c] = v;
        }
    }
    __syncthreads();

    // reducer: outputs o = tid and tid+256; o -> (b_local = o>>6, n_local = o&63)
    const int rb1l = tid >> 6;              // 0..3
    const int rnl = tid & 63;
    const int rn = n_base + rnl;

    const int woff = nh * 36 + 4 * ngrp + 2 * (ngrp >> 2);  // thread w f2 offset

    for (int s = 0; s < TT; s++) {
        const int t = dir ? (TT - 1 - s) : s;
        float2* cur = (s & 1) ? hsB : hsA;
        float2* nxt = (s & 1) ? hsA : hsB;

        // prefetch xp for this step's two outputs
        float xp1 = g_xp[dir][t][b_base + rb1l][rn];
        float xp2 = g_xp[dir][t][b_base + rb1l + 4][rn];

        // ---- mainloop: 2b x 4n per thread over this warp's 64 k2 ----
        const ull* hp = (const ull*)(cur + (size_t)(2 * bgrp) * HS2 + 64 * ks);
        const float2* wrow = ws + (size_t)(64 * ks) * WSS + woff;
        ull acc[8];
#pragma unroll
        for (int i = 0; i < 8; i++) acc[i] = 0ull;
#pragma unroll 8
        for (int kk = 0; kk < 64; kk++) {
            ull hv0 = hp[kk];
            ull hv1 = hp[kk + HS2];
            ulonglong2 w01 = *(const ulonglong2*)(wrow + (size_t)kk * WSS);
            ulonglong2 w23 = *(const ulonglong2*)(wrow + (size_t)kk * WSS + 2);
            fma2(acc[0], hv0, w01.x); fma2(acc[1], hv0, w01.y);
            fma2(acc[2], hv0, w23.x); fma2(acc[3], hv0, w23.y);
            fma2(acc[4], hv1, w01.x); fma2(acc[5], hv1, w01.y);
            fma2(acc[6], hv1, w23.x); fma2(acc[7], hv1, w23.y);
        }

        // ---- partials: red[ks][b_local*RROW + n_local] ----
        {
            ull* rp = red + (size_t)ks * RPLANE;
            int op0 = (2 * bgrp) * RROW + nh * 32 + 4 * ngrp;
            *(ulonglong2*)(rp + op0)        = make_ulonglong2(acc[0], acc[1]);
            *(ulonglong2*)(rp + op0 + 2)    = make_ulonglong2(acc[2], acc[3]);
            int op1 = op0 + RROW;
            *(ulonglong2*)(rp + op1)        = make_ulonglong2(acc[4], acc[5]);
            *(ulonglong2*)(rp + op1 + 2)    = make_ulonglong2(acc[6], acc[7]);
        }
        __syncthreads();

        // ---- 4-way reduce (2 outputs/thread) + tanh ----
        int i1 = rb1l * RROW + rnl;
        int i2 = (rb1l + 4) * RROW + rnl;
        ull s1 = red[i1], s2 = red[i2];
#pragma unroll
        for (int k = 1; k < 4; k++) {
            s1 = add2(s1, red[k * RPLANE + i1]);
            s2 = add2(s2, red[k * RPLANE + i2]);
        }
        float2 f1 = unpack2(s1), f2v = unpack2(s2);
        float v1 = tanhf(f1.x + f1.y + xp1);
        float v2 = tanhf(f2v.x + f2v.y + xp2);

        const int rb1 = b_base + rb1l, rb2 = rb1 + 4;

        if (s == TT - 1) {
            out[((size_t)rb1 * TT + t) * (2 * HH) + (size_t)dir * HH + rn] = v1;
            out[((size_t)rb2 * TT + t) * (2 * HH) + (size_t)dir * HH + rn] = v2;
            float* hT = out + (size_t)BB * TT * 2 * HH + (size_t)dir * BB * HH;
            hT[(size_t)rb1 * HH + rn] = v1;
            hT[(size_t)rb2 * HH + rn] = v2;
            break;
        }

        // write own outputs into OWN region of nxt (local smem)
        ((float*)nxt)[rb1l * (2 * HS2) + n_base + rnl] = v1;
        ((float*)nxt)[(rb1l + 4) * (2 * HS2) + n_base + rnl] = v2;
        __syncthreads();   // own region complete before push reads it

        // ---- push own 8x64 slice (128 float4) to the 7 peer CTAs ----
        {
            const unsigned nxt_u32 =
                smem_base + (unsigned)((s & 1) ? HSA_OFF : HSB_OFF);
#pragma unroll
            for (int it = 0; it < 4; it++) {
                int p = tid + 256 * it;
                if (p < 896) {
                    int rr = (ns + 1 + (p >> 7)) & 7;
                    int rem = p & 127;
                    int b = rem >> 4, j = rem & 15;
                    int f4 = b * (HS2 / 2) + 16 * ns + j;
                    float4 v = ((const float4*)nxt)[f4];
                    unsigned laddr = nxt_u32 + (unsigned)(f4 * 16);
                    unsigned raddr;
                    asm("mapa.shared::cluster.u32 %0, %1, %2;"
                        : "=r"(raddr) : "r"(laddr), "r"(rr));
                    asm volatile(
                        "st.shared::cluster.v4.f32 [%0], {%1, %2, %3, %4};"
                        :: "r"(raddr), "f"(v.x), "f"(v.y), "f"(v.z), "f"(v.w)
                        : "memory");
                }
            }
        }

        asm volatile("barrier.cluster.arrive.aligned;" ::: "memory");
        // y stores overlap the cluster barrier wait
        out[((size_t)rb1 * TT + t) * (2 * HH) + (size_t)dir * HH + rn] = v1;
        out[((size_t)rb2 * TT + t) * (2 * HH) + (size_t)dir * HH + rn] = v2;
        asm volatile("barrier.cluster.wait.aligned;" ::: "memory");
    }
}

extern "C" void kernel_launch(void* const* d_in, const int* in_sizes, int n_in,
                              void* d_out, int out_size) {
    const float* x     = (const float*)d_in[0];
    const float* h0f   = (const float*)d_in[1];
    const float* h0b   = (const float*)d_in[2];
    const float* Wxf_w = (const float*)d_in[3];
    const float* Wxf_b = (const float*)d_in[4];
    const float* Whf_w = (const float*)d_in[5];
    const float* Wxb_w = (const float*)d_in[6];
    const float* Wxb_b = (const float*)d_in[7];
    const float* Whb_w = (const float*)d_in[8];
    float* out = (float*)d_out;

    static int smem_set = 0;
    if (!smem_set) {
        cudaFuncSetAttribute(rnn_persist,
                             cudaFuncAttributeMaxDynamicSharedMemorySize,
                             SMEM_TOTAL);
        smem_set = 1;
    }

    xproj_kernel<<<dim3(HH / 64, TT, 2), 256>>>(x, Wxf_w, Wxf_b, Wxb_w, Wxb_b);
    rnn_persist<<<128, 256, SMEM_TOTAL>>>(Whf_w, Whb_w, h0f, h0b, out);
}

// round 12
// speedup vs baseline: 1.4551x; 1.3750x over previous
#include <cuda_runtime.h>

#define TT 512
#define BB 64
#define II 512
#define HH 512

// rnn_persist smem layout (element strides)
#define WSS 66      // float2 stride per k2 row of weights (64 used)
#define HS2 258     // float2 stride per batch row of h (rows at banks 0/8/16/24)
#define RPLANE 520  // ull stride per ks plane in reduction (512 used)
#define WS_BYTES (256 * WSS * 8)            // 135168
#define HS_OFF   WS_BYTES
#define HS_BYTES (8 * HS2 * 8)              // 16512
#define RED_OFF  (HS_OFF + HS_BYTES)        // 151680
#define SMEM_TOTAL (RED_OFF + 4 * RPLANE * 8)  // 168320

// Static device scratch (no allocations allowed)
__device__ float g_xp[2][TT][BB][HH];      // input projections per direction
__device__ float g_h[2][2][BB][HH];        // [dir][buf][b][h] double-buffered state
__device__ unsigned g_flag[2][8][8][32];   // [dir][bgroup][nslice] flags, 128B padded

typedef unsigned long long ull;

__device__ __forceinline__ void fma2(ull& acc, ull a, ull b) {
    asm("fma.rn.f32x2 %0, %1, %2, %0;" : "+l"(acc) : "l"(a), "l"(b));
}
__device__ __forceinline__ ull add2(ull a, ull b) {
    ull r; asm("add.rn.f32x2 %0, %1, %2;" : "=l"(r) : "l"(a), "l"(b)); return r;
}
__device__ __forceinline__ float2 unpack2(ull v) {
    float2 r; asm("mov.b64 {%0, %1}, %2;" : "=f"(r.x), "=f"(r.y) : "l"(v)); return r;
}
__device__ __forceinline__ unsigned ld_acq(const unsigned* p) {
    unsigned v; asm volatile("ld.acquire.gpu.u32 %0, [%1];" : "=r"(v) : "l"(p) : "memory");
    return v;
}
__device__ __forceinline__ void st_rel(unsigned* p, unsigned v) {
    asm volatile("st.release.gpu.u32 [%0], %1;" :: "l"(p), "r"(v) : "memory");
}

// ---------------------------------------------------------------------------
// Phase 1: xp[dir][t][b][n] = sum_i x[b][t][i] * W[n][i] + bias[n]
// ---------------------------------------------------------------------------
__global__ __launch_bounds__(256) void xproj_kernel(
    const float* __restrict__ x,
    const float* __restrict__ Wf, const float* __restrict__ bf,
    const float* __restrict__ Wb, const float* __restrict__ bbias) {
    const int dir = blockIdx.z;
    const float* __restrict__ W    = dir ? Wb : Wf;
    const float* __restrict__ bias = dir ? bbias : bf;
    const int t = blockIdx.y;
    const int n_base = blockIdx.x * 64;

    __shared__ float2 a2[8][66];   // [k2][m]
    __shared__ float2 b2[8][66];   // [k2][n]

    const int tid = threadIdx.x;
    const int w = tid >> 5, lane = tid & 31;
    const int mgrp = ((w >> 1) << 2) | (lane >> 3);  // 0..15
    const int ngrp = ((w & 1) << 3) | (lane & 7);    // 0..15
    const int m0 = mgrp << 2, n0l = ngrp << 2;

    const int lr = tid >> 2;
    const int lq = (tid & 3) << 2;
    const float* arow = x + ((size_t)lr * TT + t) * II + lq;
    const float* brow = W + (size_t)(n_base + lr) * II + lq;

    ull acc[4][4];
#pragma unroll
    for (int i = 0; i < 4; i++)
#pragma unroll
        for (int j = 0; j < 4; j++) acc[i][j] = 0ull;

    for (int st = 0; st < 32; st++) {
        float4 pa = *(const float4*)(arow + st * 16);
        float4 pb = *(const float4*)(brow + st * 16);
        __syncthreads();
        a2[(lq >> 1) + 0][lr] = make_float2(pa.x, pa.y);
        a2[(lq >> 1) + 1][lr] = make_float2(pa.z, pa.w);
        b2[(lq >> 1) + 0][lr] = make_float2(pb.x, pb.y);
        b2[(lq >> 1) + 1][lr] = make_float2(pb.z, pb.w);
        __syncthreads();
#pragma unroll
        for (int k2 = 0; k2 < 8; k2++) {
            ulonglong2 av0 = *(const ulonglong2*)&a2[k2][m0];
            ulonglong2 av1 = *(const ulonglong2*)&a2[k2][m0 + 2];
            ulonglong2 bv0 = *(const ulonglong2*)&b2[k2][n0l];
            ulonglong2 bv1 = *(const ulonglong2*)&b2[k2][n0l + 2];
            ull am[4] = {av0.x, av0.y, av1.x, av1.y};
            ull bn[4] = {bv0.x, bv0.y, bv1.x, bv1.y};
#pragma unroll
            for (int i = 0; i < 4; i++)
#pragma unroll
                for (int j = 0; j < 4; j++)
                    fma2(acc[i][j], am[i], bn[j]);
        }
    }

    float4 bv = *(const float4*)(bias + n_base + n0l);
#pragma unroll
    for (int i = 0; i < 4; i++) {
        float2 s0 = unpack2(acc[i][0]);
        float2 s1 = unpack2(acc[i][1]);
        float2 s2 = unpack2(acc[i][2]);
        float2 s3 = unpack2(acc[i][3]);
        float4 v;
        v.x = s0.x + s0.y + bv.x;
        v.y = s1.x + s1.y + bv.y;
        v.z = s2.x + s2.y + bv.z;
        v.w = s3.x + s3.y + bv.w;
        *(float4*)&g_xp[dir][t][m0 + i][n_base + n0l] = v;
    }
}

// ---------------------------------------------------------------------------
// Phase 2: persistent recurrence. 128 CTAs (64/dir), 256 threads, 1 CTA/SM.
// Per dir: 8 b-groups x 8 n-slices. CTA tile 8b x 64n, weights SMEM-resident.
// Thread tile 2b x 4n, k-split 4 (two warps per k-slice via n-halves).
// 8-CTA flag barrier per b-group; h via global L2 (proven R8 transport).
// ---------------------------------------------------------------------------
__global__ __launch_bounds__(256, 1) void rnn_persist(
    const float* __restrict__ Whf, const float* __restrict__ Whb,
    const float* __restrict__ h0f, const float* __restrict__ h0b,
    float* __restrict__ out) {
    extern __shared__ char smem[];
    float2* ws = (float2*)smem;                 // [256][WSS]
    float2* hs = (float2*)(smem + HS_OFF);      // [8][HS2]
    ull* red   = (ull*)(smem + RED_OFF);        // [4][RPLANE]

    const int cta = blockIdx.x;
    const int dir = cta & 1;
    const int rest = cta >> 1;              // 0..63
    const int bg = rest >> 3;               // b-group 0..7
    const int ns = rest & 7;                // n-slice 0..7
    const int b_base = 8 * bg;
    const int n_base = 64 * ns;
    const float* __restrict__ Wh = dir ? Whb : Whf;
    const float* __restrict__ h0 = dir ? h0b : h0f;
    const int tid = threadIdx.x;
    const int wid = tid >> 5, lane = tid & 31;
    const int ks = wid >> 1;                // k-slice 0..3 (k2 in [64ks, 64ks+64))
    const int nh = wid & 1;                 // n-half (32 n each)
    const int ngrp = lane >> 2;             // 0..7 (4 n each)
    const int bgrp = lane & 3;              // 0..3 (2 b each)

    // one-time weight fill: ws[k2][nl] = {W[n][2k2], W[n][2k2+1]}
    for (int idx = tid; idx < 64 * 256; idx += 256) {
        int nl = idx >> 8, k2 = idx & 255;
        ws[k2 * WSS + nl] =
            *(const float2*)(Wh + (size_t)(n_base + nl) * HH + 2 * k2);
    }

    // reducer: two outputs per thread: o1 = tid, o2 = tid + 256
    const int rb1l = tid >> 6;              // 0..3 (o2 adds 4)
    const int rnl = tid & 63;
    const int rn = n_base + rnl;

    // staging: row sbr (0..7), chunks c = sc + 32*i
    const int sbr = tid >> 5;
    const int sc = lane;

    const float2* wrow = ws + nh * 32 + 4 * ngrp;
    const ull* hp0 = (const ull*)(hs + (size_t)(2 * bgrp) * HS2 + 64 * ks);

    // replay-monotonic barrier base (only this CTA writes its flag)
    const unsigned base = ld_acq(&g_flag[dir][bg][ns][0]);
    __syncthreads();

    const int op0 = (2 * bgrp) * 64 + nh * 32 + 4 * ngrp;

    for (int s = 0; s < TT; s++) {
        const int t = dir ? (TT - 1 - s) : s;
        const float* __restrict__ hin =
            (s == 0) ? h0 : (const float*)g_h[dir][s & 1];
        float* __restrict__ hout = (float*)g_h[dir][(s & 1) ^ 1];

        // ---- stage 8 x 512 h into hs (1024 float4, 4 per thread) ----
#pragma unroll
        for (int i = 0; i < 4; i++) {
            int c = sc + 32 * i;
            float4 v = *(const float4*)(hin + (size_t)(b_base + sbr) * HH + 4 * c);
            *(float4*)&hs[sbr * HS2 + 2 * c] = v;
        }
        float xp1 = g_xp[dir][t][b_base + rb1l][rn];
        float xp2 = g_xp[dir][t][b_base + rb1l + 4][rn];
        __syncthreads();

        // ---- mainloop: 2b x 4n per thread over this warp's 64 k2 ----
        ull acc[8];
#pragma unroll
        for (int i = 0; i < 8; i++) acc[i] = 0ull;
        const float2* wr = wrow + (size_t)(64 * ks) * WSS;
#pragma unroll 8
        for (int kk = 0; kk < 64; kk++) {
            ull hv0 = hp0[kk];
            ull hv1 = hp0[kk + HS2];
            ulonglong2 w01 = *(const ulonglong2*)(wr + (size_t)kk * WSS);
            ulonglong2 w23 = *(const ulonglong2*)(wr + (size_t)kk * WSS + 2);
            fma2(acc[0], hv0, w01.x); fma2(acc[1], hv0, w01.y);
            fma2(acc[2], hv0, w23.x); fma2(acc[3], hv0, w23.y);
            fma2(acc[4], hv1, w01.x); fma2(acc[5], hv1, w01.y);
            fma2(acc[6], hv1, w23.x); fma2(acc[7], hv1, w23.y);
        }

        // ---- partials: red[ks][op] ----
        {
            ull* rp = red + (size_t)ks * RPLANE;
            *(ulonglong2*)(rp + op0)       = make_ulonglong2(acc[0], acc[1]);
            *(ulonglong2*)(rp + op0 + 2)   = make_ulonglong2(acc[2], acc[3]);
            *(ulonglong2*)(rp + op0 + 64)  = make_ulonglong2(acc[4], acc[5]);
            *(ulonglong2*)(rp + op0 + 66)  = make_ulonglong2(acc[6], acc[7]);
        }
        __syncthreads();

        // ---- 4-way reduce (2 outputs/thread) + tanh ----
        ull s1 = red[tid], s2 = red[tid + 256];
#pragma unroll
        for (int k = 1; k < 4; k++) {
            s1 = add2(s1, red[k * RPLANE + tid]);
            s2 = add2(s2, red[k * RPLANE + tid + 256]);
        }
        float2 f1 = unpack2(s1), f2v = unpack2(s2);
        float v1 = tanhf(f1.x + f1.y + xp1);
        float v2 = tanhf(f2v.x + f2v.y + xp2);
        const int rb1 = b_base + rb1l, rb2 = rb1 + 4;

        if (s < TT - 1) {
            hout[(size_t)rb1 * HH + rn] = v1;
            hout[(size_t)rb2 * HH + rn] = v2;
            __syncthreads();                 // all hout writes issued
            if (tid == 0) st_rel(&g_flag[dir][bg][ns][0], base + s + 1);
            // y stores off the inter-CTA critical path
            out[((size_t)rb1 * TT + t) * (2 * HH) + (size_t)dir * HH + rn] = v1;
            out[((size_t)rb2 * TT + t) * (2 * HH) + (size_t)dir * HH + rn] = v2;
            // poll the 8 flags of this b-group
            if (tid < 8) {
                const unsigned tgt = base + (unsigned)(s + 1);
                const unsigned* f = &g_flag[dir][bg][tid][0];
                while (ld_acq(f) < tgt) {}
            }
            __syncthreads();
        } else {
            out[((size_t)rb1 * TT + t) * (2 * HH) + (size_t)dir * HH + rn] = v1;
            out[((size_t)rb2 * TT + t) * (2 * HH) + (size_t)dir * HH + rn] = v2;
            float* hT = out + (size_t)BB * TT * 2 * HH + (size_t)dir * BB * HH;
            hT[(size_t)rb1 * HH + rn] = v1;
            hT[(size_t)rb2 * HH + rn] = v2;
        }
    }
}

extern "C" void kernel_launch(void* const* d_in, const int* in_sizes, int n_in,
                              void* d_out, int out_size) {
    const float* x     = (const float*)d_in[0];
    const float* h0f   = (const float*)d_in[1];
    const float* h0b   = (const float*)d_in[2];
    const float* Wxf_w = (const float*)d_in[3];
    const float* Wxf_b = (const float*)d_in[4];
    const float* Whf_w = (const float*)d_in[5];
    const float* Wxb_w = (const float*)d_in[6];
    const float* Wxb_b = (const float*)d_in[7];
    const float* Whb_w = (const float*)d_in[8];
    float* out = (float*)d_out;

    static int smem_set = 0;
    if (!smem_set) {
        cudaFuncSetAttribute(rnn_persist,
                             cudaFuncAttributeMaxDynamicSharedMemorySize,
                             SMEM_TOTAL);
        smem_set = 1;
    }

    xproj_kernel<<<dim3(HH / 64, TT, 2), 256>>>(x, Wxf_w, Wxf_b, Wxb_w, Wxb_b);
    rnn_persist<<<128, 256, SMEM_TOTAL>>>(Whf_w, Whb_w, h0f, h0b, out);
}

// round 13
// speedup vs baseline: 1.6081x; 1.1052x over previous
#include <cuda_runtime.h>

#define TT 512
#define BB 64
#define II 512
#define HH 512

// rnn_persist smem layout (element strides)
#define HS2 258     // float2 stride per batch row of h
#define RP  520     // ull stride per ks plane in reduction (512 used)
#define RED_OFF (8 * HS2 * 8)                  // 16512
#define SMEM_TOTAL (RED_OFF + 16 * RP * 8)     // 83072

// Static device scratch (no allocations allowed)
__device__ float g_xp[2][TT][BB][HH];      // input projections per direction
__device__ float g_h[2][2][BB][HH];        // [dir][buf][b][h] double-buffered state
__device__ unsigned g_flag[2][8][8][32];   // [dir][bgroup][nslice] flags, 128B padded

typedef unsigned long long ull;

__device__ __forceinline__ void fma2(ull& acc, ull a, ull b) {
    asm("fma.rn.f32x2 %0, %1, %2, %0;" : "+l"(acc) : "l"(a), "l"(b));
}
__device__ __forceinline__ ull add2(ull a, ull b) {
    ull r; asm("add.rn.f32x2 %0, %1, %2;" : "=l"(r) : "l"(a), "l"(b)); return r;
}
__device__ __forceinline__ float2 unpack2(ull v) {
    float2 r; asm("mov.b64 {%0, %1}, %2;" : "=f"(r.x), "=f"(r.y) : "l"(v)); return r;
}
__device__ __forceinline__ unsigned ld_acq(const unsigned* p) {
    unsigned v; asm volatile("ld.acquire.gpu.u32 %0, [%1];" : "=r"(v) : "l"(p) : "memory");
    return v;
}
__device__ __forceinline__ void st_rel(unsigned* p, unsigned v) {
    asm volatile("st.release.gpu.u32 [%0], %1;" :: "l"(p), "r"(v) : "memory");
}

// ---------------------------------------------------------------------------
// Phase 1: xp[dir][t][b][n] = sum_i x[b][t][i] * W[n][i] + bias[n]
// ---------------------------------------------------------------------------
__global__ __launch_bounds__(256) void xproj_kernel(
    const float* __restrict__ x,
    const float* __restrict__ Wf, const float* __restrict__ bf,
    const float* __restrict__ Wb, const float* __restrict__ bbias) {
    const int dir = blockIdx.z;
    const float* __restrict__ W    = dir ? Wb : Wf;
    const float* __restrict__ bias = dir ? bbias : bf;
    const int t = blockIdx.y;
    const int n_base = blockIdx.x * 64;

    __shared__ float2 a2[8][66];   // [k2][m]
    __shared__ float2 b2[8][66];   // [k2][n]

    const int tid = threadIdx.x;
    const int w = tid >> 5, lane = tid & 31;
    const int mgrp = ((w >> 1) << 2) | (lane >> 3);  // 0..15
    const int ngrp = ((w & 1) << 3) | (lane & 7);    // 0..15
    const int m0 = mgrp << 2, n0l = ngrp << 2;

    const int lr = tid >> 2;
    const int lq = (tid & 3) << 2;
    const float* arow = x + ((size_t)lr * TT + t) * II + lq;
    const float* brow = W + (size_t)(n_base + lr) * II + lq;

    ull acc[4][4];
#pragma unroll
    for (int i = 0; i < 4; i++)
#pragma unroll
        for (int j = 0; j < 4; j++) acc[i][j] = 0ull;

    for (int st = 0; st < 32; st++) {
        float4 pa = *(const float4*)(arow + st * 16);
        float4 pb = *(const float4*)(brow + st * 16);
        __syncthreads();
        a2[(lq >> 1) + 0][lr] = make_float2(pa.x, pa.y);
        a2[(lq >> 1) + 1][lr] = make_float2(pa.z, pa.w);
        b2[(lq >> 1) + 0][lr] = make_float2(pb.x, pb.y);
        b2[(lq >> 1) + 1][lr] = make_float2(pb.z, pb.w);
        __syncthreads();
#pragma unroll
        for (int k2 = 0; k2 < 8; k2++) {
            ulonglong2 av0 = *(const ulonglong2*)&a2[k2][m0];
            ulonglong2 av1 = *(const ulonglong2*)&a2[k2][m0 + 2];
            ulonglong2 bv0 = *(const ulonglong2*)&b2[k2][n0l];
            ulonglong2 bv1 = *(const ulonglong2*)&b2[k2][n0l + 2];
            ull am[4] = {av0.x, av0.y, av1.x, av1.y};
            ull bn[4] = {bv0.x, bv0.y, bv1.x, bv1.y};
#pragma unroll
            for (int i = 0; i < 4; i++)
#pragma unroll
                for (int j = 0; j < 4; j++)
                    fma2(acc[i][j], am[i], bn[j]);
        }
    }

    float4 bv = *(const float4*)(bias + n_base + n0l);
#pragma unroll
    for (int i = 0; i < 4; i++) {
        float2 s0 = unpack2(acc[i][0]);
        float2 s1 = unpack2(acc[i][1]);
        float2 s2 = unpack2(acc[i][2]);
        float2 s3 = unpack2(acc[i][3]);
        float4 v;
        v.x = s0.x + s0.y + bv.x;
        v.y = s1.x + s1.y + bv.y;
        v.z = s2.x + s2.y + bv.z;
        v.w = s3.x + s3.y + bv.w;
        *(float4*)&g_xp[dir][t][m0 + i][n_base + n0l] = v;
    }
}

// ---------------------------------------------------------------------------
// Phase 2: persistent recurrence. 128 CTAs (64/dir), 512 threads, 1 CTA/SM.
// Per dir: 8 b-groups x 8 n-slices; CTA tile 8b x 64n.
// WEIGHTS LIVE IN REGISTERS: k-split 16 (warp = 32-k slice), thread = 2n x 8b,
// 32 weight-pairs per thread resident for all 512 steps. Mainloop smem traffic
// is h only (full-warp broadcast LDS.64). 16-plane smem reduction.
// 8-CTA flag barrier per b-group (proven R8/R11 transport).
// ---------------------------------------------------------------------------
__global__ __launch_bounds__(512, 1) void rnn_persist(
    const float* __restrict__ Whf, const float* __restrict__ Whb,
    const float* __restrict__ h0f, const float* __restrict__ h0b,
    float* __restrict__ out) {
    extern __shared__ char smem[];
    float2* hs = (float2*)smem;                 // [8][HS2]
    ull* red   = (ull*)(smem + RED_OFF);        // [16][RP]

    const int cta = blockIdx.x;
    const int dir = cta & 1;
    const int rest = cta >> 1;              // 0..63
    const int bg = rest >> 3;               // b-group 0..7
    const int ns = rest & 7;                // n-slice 0..7
    const int b_base = 8 * bg;
    const int n_base = 64 * ns;
    const float* __restrict__ Wh = dir ? Whb : Whf;
    const float* __restrict__ h0 = dir ? h0b : h0f;
    const int tid = threadIdx.x;
    const int wid = tid >> 5;               // warp = k-slice 0..15 (16 k2 each)
    const int lane = tid & 31;
    const int n0 = n_base + 2 * lane;       // this thread's two n columns

    // ---- one-time weight fill into REGISTERS ----
    // w0[kkk] = {W[n0][2k2], W[n0][2k2+1]},  w1 for n0+1, k2 = 16*wid + kkk
    ull w0[16], w1[16];
#pragma unroll
    for (int kkk = 0; kkk < 16; kkk++) {
        int k2 = 16 * wid + kkk;
        w0[kkk] = *(const ull*)(Wh + (size_t)n0 * HH + 2 * k2);
        w1[kkk] = *(const ull*)(Wh + (size_t)(n0 + 1) * HH + 2 * k2);
    }

    // reducer: output o = tid -> (b_local = tid>>6, n_local = tid&63)
    const int rbl = tid >> 6;
    const int rnl = tid & 63;
    const int rn = n_base + rnl;

    // replay-monotonic barrier base (only this CTA writes its flag)
    const unsigned base = ld_acq(&g_flag[dir][bg][ns][0]);

    const ull* hwarp = (const ull*)hs + 16 * wid;   // this warp's k2 window

    for (int s = 0; s < TT; s++) {
        const int t = dir ? (TT - 1 - s) : s;
        const float* __restrict__ hin =
            (s == 0) ? h0 : (const float*)g_h[dir][s & 1];
        float* __restrict__ hout = (float*)g_h[dir][(s & 1) ^ 1];

        // ---- stage 8 x 512 h into hs (1024 float4, 2 per thread) ----
#pragma unroll
        for (int i = 0; i < 2; i++) {
            int idx = tid + 512 * i;
            int b = idx >> 7, c = idx & 127;
            float4 v = *(const float4*)(hin + (size_t)(b_base + b) * HH + 4 * c);
            *(float4*)&hs[b * HS2 + 2 * c] = v;
        }
        float xpv = g_xp[dir][t][b_base + rbl][rn];
        __syncthreads();

        // ---- mainloop: 2n x 8b per thread; w in regs; h broadcast LDS ----
        ull acc[16];
#pragma unroll
        for (int i = 0; i < 16; i++) acc[i] = 0ull;
#pragma unroll
        for (int kkk = 0; kkk < 16; kkk++) {
            ull ha = hwarp[0 * HS2 + kkk];
            ull hb = hwarp[1 * HS2 + kkk];
            ull hc = hwarp[2 * HS2 + kkk];
            ull hd = hwarp[3 * HS2 + kkk];
            ull he = hwarp[4 * HS2 + kkk];
            ull hf = hwarp[5 * HS2 + kkk];
            ull hg = hwarp[6 * HS2 + kkk];
            ull hh = hwarp[7 * HS2 + kkk];
            fma2(acc[0], ha, w0[kkk]); fma2(acc[8],  ha, w1[kkk]);
            fma2(acc[1], hb, w0[kkk]); fma2(acc[9],  hb, w1[kkk]);
            fma2(acc[2], hc, w0[kkk]); fma2(acc[10], hc, w1[kkk]);
            fma2(acc[3], hd, w0[kkk]); fma2(acc[11], hd, w1[kkk]);
            fma2(acc[4], he, w0[kkk]); fma2(acc[12], he, w1[kkk]);
            fma2(acc[5], hf, w0[kkk]); fma2(acc[13], hf, w1[kkk]);
            fma2(acc[6], hg, w0[kkk]); fma2(acc[14], hg, w1[kkk]);
            fma2(acc[7], hh, w0[kkk]); fma2(acc[15], hh, w1[kkk]);
        }

        // ---- partials: red[wid][b*64 + 2*lane + j] = acc[j*8+b] ----
        {
            ull* rp = red + (size_t)wid * RP + 2 * lane;
#pragma unroll
            for (int b = 0; b < 8; b++)
                *(ulonglong2*)(rp + b * 64) =
                    make_ulonglong2(acc[b], acc[8 + b]);
        }
        __syncthreads();

        // ---- 16-way reduce (1 output/thread) + tanh ----
        ull ssum = red[tid];
#pragma unroll
        for (int k = 1; k < 16; k++) ssum = add2(ssum, red[k * RP + tid]);
        float2 f = unpack2(ssum);
        float v = tanhf(f.x + f.y + xpv);
        const int rb = b_base + rbl;

        if (s < TT - 1) {
            hout[(size_t)rb * HH + rn] = v;
            __syncthreads();                 // all hout writes issued
            if (tid == 0) st_rel(&g_flag[dir][bg][ns][0], base + s + 1);
            // y store off the inter-CTA critical path
            out[((size_t)rb * TT + t) * (2 * HH) + (size_t)dir * HH + rn] = v;
            // poll the 8 flags of this b-group
            if (tid < 8) {
                const unsigned tgt = base + (unsigned)(s + 1);
                const unsigned* f8 = &g_flag[dir][bg][tid][0];
                while (ld_acq(f8) < tgt) {}
            }
            __syncthreads();
        } else {
            out[((size_t)rb * TT + t) * (2 * HH) + (size_t)dir * HH + rn] = v;
            float* hT = out + (size_t)BB * TT * 2 * HH + (size_t)dir * BB * HH;
            hT[(size_t)rb * HH + rn] = v;
        }
    }
}

extern "C" void kernel_launch(void* const* d_in, const int* in_sizes, int n_in,
                              void* d_out, int out_size) {
    const float* x     = (const float*)d_in[0];
    const float* h0f   = (const float*)d_in[1];
    const float* h0b   = (const float*)d_in[2];
    const float* Wxf_w = (const float*)d_in[3];
    const float* Wxf_b = (const float*)d_in[4];
    const float* Whf_w = (const float*)d_in[5];
    const float* Wxb_w = (const float*)d_in[6];
    const float* Wxb_b = (const float*)d_in[7];
    const float* Whb_w = (const float*)d_in[8];
    float* out = (float*)d_out;

    static int smem_set = 0;
    if (!smem_set) {
        cudaFuncSetAttribute(rnn_persist,
                             cudaFuncAttributeMaxDynamicSharedMemorySize,
                             SMEM_TOTAL);
        smem_set = 1;
    }

    xproj_kernel<<<dim3(HH / 64, TT, 2), 256>>>(x, Wxf_w, Wxf_b, Wxb_w, Wxb_b);
    rnn_persist<<<128, 512, SMEM_TOTAL>>>(Whf_w, Whb_w, h0f, h0b, out);
}